// round 1
// baseline (speedup 1.0000x reference)
#include <cuda_runtime.h>

#define E 64
#define H 8
#define HE 512
#define MAX_TOKENS 16384

// scratch (device globals: no cudaMalloc allowed)
__device__ __align__(16) float g_q[MAX_TOKENS * HE];
__device__ __align__(16) float g_k[MAX_TOKENS * HE];
__device__ __align__(16) float g_v[MAX_TOKENS * HE];
__device__ __align__(16) float g_res[MAX_TOKENS * HE];

// ---------------------------------------------------------------------------
// Generic tiled GEMM:  O[m][n] = sum_k A[m*lda+k] * B[n*ldb+k] + bias[n]
// BM=128, BN=64, BK=64, 256 threads, 8x4 micro-tile.
// sel: 0/1/2 -> write g_q/g_k/g_v ; 3 -> A = g_res, write Oext
// ---------------------------------------------------------------------------
__global__ void __launch_bounds__(256)
gemm_bias_kernel(const float* __restrict__ Aext, int lda,
                 const float* __restrict__ B, int ldb,
                 const float* __restrict__ bias,
                 float* __restrict__ Oext,
                 int sel, int ldo, int Ktot)
{
    const float* A = (sel == 3) ? g_res : Aext;
    float* Obase = (sel == 0) ? g_q : (sel == 1) ? g_k : (sel == 2) ? g_v : Oext;

    __shared__ __align__(16) float As[64][128];
    __shared__ __align__(16) float Bs[64][64];

    const int t  = threadIdx.x;
    const int m0 = blockIdx.y * 128;
    const int n0 = blockIdx.x * 64;
    const int r  = t >> 4;
    const int c4 = t & 15;
    const int tx = t & 15;
    const int ty = t >> 4;

    float acc[8][4];
#pragma unroll
    for (int i = 0; i < 8; ++i)
#pragma unroll
        for (int j = 0; j < 4; ++j) acc[i][j] = 0.0f;

    for (int kc = 0; kc < Ktot; kc += 64) {
        __syncthreads();
        // A tile: 128 rows x 64 k  (stored k-major)
#pragma unroll
        for (int it = 0; it < 8; ++it) {
            int m = r + it * 16;
            const float4 va = *(const float4*)(A + (size_t)(m0 + m) * lda + kc + c4 * 4);
            As[c4 * 4 + 0][m] = va.x;
            As[c4 * 4 + 1][m] = va.y;
            As[c4 * 4 + 2][m] = va.z;
            As[c4 * 4 + 3][m] = va.w;
        }
        // B tile: 64 rows x 64 k
#pragma unroll
        for (int it = 0; it < 4; ++it) {
            int n = r + it * 16;
            const float4 vb = *(const float4*)(B + (size_t)(n0 + n) * ldb + kc + c4 * 4);
            Bs[c4 * 4 + 0][n] = vb.x;
            Bs[c4 * 4 + 1][n] = vb.y;
            Bs[c4 * 4 + 2][n] = vb.z;
            Bs[c4 * 4 + 3][n] = vb.w;
        }
        __syncthreads();
#pragma unroll 8
        for (int k = 0; k < 64; ++k) {
            float a[8], b[4];
            *(float4*)&a[0] = *(const float4*)&As[k][ty * 8];
            *(float4*)&a[4] = *(const float4*)&As[k][ty * 8 + 4];
            *(float4*)&b[0] = *(const float4*)&Bs[k][tx * 4];
#pragma unroll
            for (int i = 0; i < 8; ++i)
#pragma unroll
                for (int j = 0; j < 4; ++j)
                    acc[i][j] = fmaf(a[i], b[j], acc[i][j]);
        }
    }

    float bv[4];
#pragma unroll
    for (int j = 0; j < 4; ++j) bv[j] = bias[n0 + tx * 4 + j];
#pragma unroll
    for (int i = 0; i < 8; ++i) {
        float4 o;
        o.x = acc[i][0] + bv[0];
        o.y = acc[i][1] + bv[1];
        o.z = acc[i][2] + bv[2];
        o.w = acc[i][3] + bv[3];
        *(float4*)(Obase + (size_t)(m0 + ty * 8 + i) * ldo + n0 + tx * 4) = o;
    }
}

// ---------------------------------------------------------------------------
// Per-token attention + alpha-entmax + value mix.
// 256 threads = 4 tokens/CTA; thread (token, i) owns score row i (64 regs).
// ---------------------------------------------------------------------------
__global__ void __launch_bounds__(256)
attn_kernel(const float* __restrict__ alpha_p)
{
    __shared__ __align__(16) float ks[4][HE];
    __shared__ __align__(16) float vsm[4][HE];

    const int t = threadIdx.x;
    const int tl = t >> 6;       // token within CTA
    const int i  = t & 63;       // score row
    const int base = blockIdx.x * 4;
    const size_t token = (size_t)(base + tl);

    // cooperative load of k,v for 4 tokens (512 float4 each)
#pragma unroll
    for (int it = 0; it < 2; ++it) {
        int idx = t + it * 256;
        ((float4*)ks)[idx]  = ((const float4*)(g_k + (size_t)base * HE))[idx];
        ((float4*)vsm)[idx] = ((const float4*)(g_v + (size_t)base * HE))[idx];
    }

    const float alpha = *alpha_p;
    const float am1 = alpha - 1.0f;
    const float inv = 1.0f / am1;
    const float qscale = am1 * 0.125f;   // fold am1 * (1/sqrt(64)) into q

    float qr[H];
#pragma unroll
    for (int h = 0; h < H; ++h)
        qr[h] = g_q[token * HE + h * 64 + i] * qscale;

    __syncthreads();

    // s[j] = Xa[i][j] = am1 * dot[i][j]/8
    float s[64];
#pragma unroll
    for (int j = 0; j < 64; ++j) s[j] = 0.0f;
#pragma unroll
    for (int h = 0; h < H; ++h) {
        const float qh = qr[h];
#pragma unroll
        for (int j4 = 0; j4 < 16; ++j4) {
            float4 kk = *(const float4*)&ks[tl][h * 64 + j4 * 4];
            s[j4 * 4 + 0] = fmaf(qh, kk.x, s[j4 * 4 + 0]);
            s[j4 * 4 + 1] = fmaf(qh, kk.y, s[j4 * 4 + 1]);
            s[j4 * 4 + 2] = fmaf(qh, kk.z, s[j4 * 4 + 2]);
            s[j4 * 4 + 3] = fmaf(qh, kk.w, s[j4 * 4 + 3]);
        }
    }

    float mx = s[0];
#pragma unroll
    for (int j = 1; j < 64; ++j) mx = fmaxf(mx, s[j]);

    if (fabsf(inv - 2.0f) < 1e-4f) {
        // alpha = 1.5: p(z) = relu(z)^2.  f(tau)=sum p(Xa-tau)-1 is convex,
        // decreasing. Newton from tau0=mx-1 is monotone from below; finish
        // with the exact quadratic solve on the current active set.
        float tau = mx - 1.0f;
        const float tau_hi = mx - 0.125f;   // mx - (1/64)^{0.5}
#pragma unroll 1
        for (int it = 0; it < 8; ++it) {
            float s1a = 0.f, s1b = 0.f, s2a = 0.f, s2b = 0.f;
#pragma unroll
            for (int j = 0; j < 64; j += 2) {
                float za = fmaxf(s[j]     - tau, 0.0f);
                float zb = fmaxf(s[j + 1] - tau, 0.0f);
                s1a += za; s1b += zb;
                s2a = fmaf(za, za, s2a);
                s2b = fmaf(zb, zb, s2b);
            }
            float s1 = s1a + s1b;
            float s2 = s2a + s2b;
            tau = fminf(tau + __fdividef(s2 - 1.0f, 2.0f * s1), tau_hi);
        }
        // exact solve: k*tau^2 - 2*S1*tau + (S2-1) = 0 on the active set
        float s1 = 0.f, s2 = 0.f, cnt = 0.f;
#pragma unroll
        for (int j = 0; j < 64; ++j) {
            float z = s[j] - tau;
            float m = fmaxf(z, 0.0f);
            s1 += m;
            s2 = fmaf(m, m, s2);
            cnt += (z > 0.0f) ? 1.0f : 0.0f;
        }
        float S1 = fmaf(tau, cnt, s1);
        float S2 = s2 + 2.0f * tau * s1 + tau * tau * cnt;
        float disc = fmaxf(fmaf(-cnt, S2 - 1.0f, S1 * S1), 0.0f);
        tau = __fdividef(S1 - sqrtf(disc), cnt);

        float sum = 0.f;
#pragma unroll
        for (int j = 0; j < 64; ++j) {
            float m = fmaxf(s[j] - tau, 0.0f);
            s[j] = m * m;
            sum += s[j];
        }
        float rn = __fdividef(1.0f, sum);
#pragma unroll
        for (int j = 0; j < 64; ++j) s[j] *= rn;
    } else {
        // generic alpha: faithful 50-iter bisection (mirrors reference)
        float tau_lo = mx - 1.0f;
        float dm = (mx - __powf(1.0f / 64.0f, am1)) - tau_lo;
        float f_lo = -1.0f;
#pragma unroll
        for (int j = 0; j < 64; ++j) {
            float z = s[j] - tau_lo;
            if (z > 0.0f) f_lo += __powf(fmaxf(z, 1e-30f), inv);
        }
        float tau_m = tau_lo;
#pragma unroll 1
        for (int it = 0; it < 50; ++it) {
            dm *= 0.5f;
            tau_m = tau_lo + dm;
            float f_m = -1.0f;
#pragma unroll
            for (int j = 0; j < 64; ++j) {
                float z = s[j] - tau_m;
                if (z > 0.0f) f_m += __powf(fmaxf(z, 1e-30f), inv);
            }
            if (f_m * f_lo >= 0.0f) tau_lo = tau_m;
        }
        float sum = 0.f;
#pragma unroll
        for (int j = 0; j < 64; ++j) {
            float z = s[j] - tau_m;
            s[j] = (z > 0.0f) ? __powf(fmaxf(z, 1e-30f), inv) : 0.0f;
            sum += s[j];
        }
        float rn = __fdividef(1.0f, sum);
#pragma unroll
        for (int j = 0; j < 64; ++j) s[j] *= rn;
    }

    // res[h][i] = sum_j att[i][j] * v[h][j]
    float r[H];
#pragma unroll
    for (int h = 0; h < H; ++h) r[h] = 0.0f;
#pragma unroll
    for (int h = 0; h < H; ++h) {
        float ra = 0.f, rb = 0.f;
#pragma unroll
        for (int j4 = 0; j4 < 16; ++j4) {
            float4 vv = *(const float4*)&vsm[tl][h * 64 + j4 * 4];
            ra = fmaf(s[j4 * 4 + 0], vv.x, ra);
            rb = fmaf(s[j4 * 4 + 1], vv.y, rb);
            ra = fmaf(s[j4 * 4 + 2], vv.z, ra);
            rb = fmaf(s[j4 * 4 + 3], vv.w, rb);
        }
        r[h] = ra + rb;
    }
#pragma unroll
    for (int h = 0; h < H; ++h)
        g_res[token * HE + h * 64 + i] = r[h];
}

// ---------------------------------------------------------------------------
extern "C" void kernel_launch(void* const* d_in, const int* in_sizes, int n_in,
                              void* d_out, int out_size)
{
    const float* x     = (const float*)d_in[0];
    const float* alpha = (const float*)d_in[1];
    const float* Wk    = (const float*)d_in[2];
    const float* bk    = (const float*)d_in[3];
    const float* Wq    = (const float*)d_in[4];
    const float* bq    = (const float*)d_in[5];
    const float* Wv    = (const float*)d_in[6];
    const float* bv    = (const float*)d_in[7];
    const float* Wu    = (const float*)d_in[8];
    const float* bu    = (const float*)d_in[9];

    const int tokens = in_sizes[0] / E;   // 16384

    dim3 gproj(HE / 64, tokens / 128);    // (8, 128)
    gemm_bias_kernel<<<gproj, 256>>>(x, E, Wq, E, bq, nullptr, 0, HE, E);
    gemm_bias_kernel<<<gproj, 256>>>(x, E, Wk, E, bk, nullptr, 1, HE, E);
    gemm_bias_kernel<<<gproj, 256>>>(x, E, Wv, E, bv, nullptr, 2, HE, E);

    attn_kernel<<<tokens / 4, 256>>>(alpha);

    dim3 gout(1, tokens / 128);
    gemm_bias_kernel<<<gout, 256>>>(nullptr, HE, Wu, HE, bu, (float*)d_out, 3, E, HE);
}

// round 2
// speedup vs baseline: 1.2521x; 1.2521x over previous
#include <cuda_runtime.h>

#define E 64
#define H 8
#define HE 512
#define MAX_TOKENS 16384

typedef unsigned long long ull;

__device__ __forceinline__ ull pack2(float lo, float hi) {
    ull r; asm("mov.b64 %0, {%1, %2};" : "=l"(r) : "f"(lo), "f"(hi)); return r;
}
__device__ __forceinline__ float2 unpack2(ull v) {
    float2 f; asm("mov.b64 {%0, %1}, %2;" : "=f"(f.x), "=f"(f.y) : "l"(v)); return f;
}
__device__ __forceinline__ ull ffma2(ull a, ull b, ull c) {
    ull d; asm("fma.rn.f32x2 %0, %1, %2, %3;" : "=l"(d) : "l"(a), "l"(b), "l"(c)); return d;
}

// scratch (device globals: no cudaMalloc allowed)
__device__ __align__(16) float g_q[MAX_TOKENS * HE];
__device__ __align__(16) float g_k[MAX_TOKENS * HE];
__device__ __align__(16) float g_v[MAX_TOKENS * HE];
__device__ __align__(16) float g_res[MAX_TOKENS * HE];

// ---------------------------------------------------------------------------
// Fused QKV GEMM.  O[m][n] = sum_k x[m][k] * W[n][k] + b[n]
// BM=128, BN=64, BK=32 (2 chunks), 256 threads, 8x4 micro-tile, f32x2 packed.
// grid: (24, tokens/128); blockIdx.x selects which W (8 n-blocks per W).
// ---------------------------------------------------------------------------
__global__ void __launch_bounds__(256)
qkv_gemm(const float* __restrict__ x,
         const float* __restrict__ Wq, const float* __restrict__ bq,
         const float* __restrict__ Wk, const float* __restrict__ bk,
         const float* __restrict__ Wv, const float* __restrict__ bv)
{
    __shared__ __align__(16) float As[32][132];
    __shared__ __align__(16) float Bs[32][68];

    const int t  = threadIdx.x;
    const int m0 = blockIdx.y * 128;
    const int nblk = blockIdx.x;           // 0..23
    const int widx = nblk >> 3;
    const int n0 = (nblk & 7) * 64;        // within the selected W

    const float* W    = (widx == 0) ? Wq : (widx == 1) ? Wk : Wv;
    const float* bias = (widx == 0) ? bq : (widx == 1) ? bk : bv;
    float* O          = (widx == 0) ? g_q : (widx == 1) ? g_k : g_v;

    const int mg = (t >> 4) * 8;   // 8 m rows
    const int ng = (t & 15) * 4;   // 4 n cols

    ull acc[4][4];
#pragma unroll
    for (int p = 0; p < 4; ++p)
#pragma unroll
        for (int j = 0; j < 4; ++j) acc[p][j] = 0ull;

    for (int kc = 0; kc < E; kc += 32) {
        __syncthreads();
        // A tile: 128 rows x 32 k (k-major in smem)
        {
            const int row = t >> 1, seg = t & 1;
            const float4* src = (const float4*)(x + (size_t)(m0 + row) * E + kc + seg * 16);
#pragma unroll
            for (int i = 0; i < 4; ++i) {
                float4 v = src[i];
                int k = seg * 16 + i * 4;
                As[k + 0][row] = v.x; As[k + 1][row] = v.y;
                As[k + 2][row] = v.z; As[k + 3][row] = v.w;
            }
        }
        // B tile: 64 rows x 32 k
        {
            const int row = t >> 2, seg = t & 3;
            const float4* src = (const float4*)(W + (size_t)(n0 + row) * E + kc + seg * 8);
#pragma unroll
            for (int i = 0; i < 2; ++i) {
                float4 v = src[i];
                int k = seg * 8 + i * 4;
                Bs[k + 0][row] = v.x; Bs[k + 1][row] = v.y;
                Bs[k + 2][row] = v.z; Bs[k + 3][row] = v.w;
            }
        }
        __syncthreads();
#pragma unroll 8
        for (int k = 0; k < 32; ++k) {
            ull a[4];
            a[0] = *(const ull*)&As[k][mg + 0];
            a[1] = *(const ull*)&As[k][mg + 2];
            a[2] = *(const ull*)&As[k][mg + 4];
            a[3] = *(const ull*)&As[k][mg + 6];
            float4 b = *(const float4*)&Bs[k][ng];
            ull b2[4] = { pack2(b.x, b.x), pack2(b.y, b.y),
                          pack2(b.z, b.z), pack2(b.w, b.w) };
#pragma unroll
            for (int p = 0; p < 4; ++p)
#pragma unroll
                for (int j = 0; j < 4; ++j)
                    acc[p][j] = ffma2(a[p], b2[j], acc[p][j]);
        }
    }

    float bvv[4];
#pragma unroll
    for (int j = 0; j < 4; ++j) bvv[j] = bias[n0 + ng + j];
#pragma unroll
    for (int p = 0; p < 4; ++p) {
        float2 c0 = unpack2(acc[p][0]);
        float2 c1 = unpack2(acc[p][1]);
        float2 c2 = unpack2(acc[p][2]);
        float2 c3 = unpack2(acc[p][3]);
        float4 o0 = { c0.x + bvv[0], c1.x + bvv[1], c2.x + bvv[2], c3.x + bvv[3] };
        float4 o1 = { c0.y + bvv[0], c1.y + bvv[1], c2.y + bvv[2], c3.y + bvv[3] };
        *(float4*)(O + (size_t)(m0 + mg + 2 * p)     * HE + n0 + ng) = o0;
        *(float4*)(O + (size_t)(m0 + mg + 2 * p + 1) * HE + n0 + ng) = o1;
    }
}

// ---------------------------------------------------------------------------
// Output GEMM: out[m][n] = sum_k g_res[m][k] * Wu[n][k] + bu[n]
// BM=64, BN=64, BK=32 (16 chunks), 256 threads, 4x4 micro-tile, f32x2 packed.
// ---------------------------------------------------------------------------
__global__ void __launch_bounds__(256)
out_gemm(const float* __restrict__ Wu, const float* __restrict__ bu,
         float* __restrict__ out)
{
    __shared__ __align__(16) float As[32][68];
    __shared__ __align__(16) float Bs[32][68];

    const int t  = threadIdx.x;
    const int m0 = blockIdx.x * 64;
    const int mg = (t >> 4) * 4;
    const int ng = (t & 15) * 4;

    ull acc[2][4];
#pragma unroll
    for (int p = 0; p < 2; ++p)
#pragma unroll
        for (int j = 0; j < 4; ++j) acc[p][j] = 0ull;

    for (int kc = 0; kc < HE; kc += 32) {
        __syncthreads();
        {
            const int row = t >> 2, seg = t & 3;
            const float4* src = (const float4*)(g_res + (size_t)(m0 + row) * HE + kc + seg * 8);
#pragma unroll
            for (int i = 0; i < 2; ++i) {
                float4 v = src[i];
                int k = seg * 8 + i * 4;
                As[k + 0][row] = v.x; As[k + 1][row] = v.y;
                As[k + 2][row] = v.z; As[k + 3][row] = v.w;
            }
        }
        {
            const int row = t >> 2, seg = t & 3;
            const float4* src = (const float4*)(Wu + (size_t)row * HE + kc + seg * 8);
#pragma unroll
            for (int i = 0; i < 2; ++i) {
                float4 v = src[i];
                int k = seg * 8 + i * 4;
                Bs[k + 0][row] = v.x; Bs[k + 1][row] = v.y;
                Bs[k + 2][row] = v.z; Bs[k + 3][row] = v.w;
            }
        }
        __syncthreads();
#pragma unroll 8
        for (int k = 0; k < 32; ++k) {
            ull a0 = *(const ull*)&As[k][mg + 0];
            ull a1 = *(const ull*)&As[k][mg + 2];
            float4 b = *(const float4*)&Bs[k][ng];
            ull b2[4] = { pack2(b.x, b.x), pack2(b.y, b.y),
                          pack2(b.z, b.z), pack2(b.w, b.w) };
#pragma unroll
            for (int j = 0; j < 4; ++j) {
                acc[0][j] = ffma2(a0, b2[j], acc[0][j]);
                acc[1][j] = ffma2(a1, b2[j], acc[1][j]);
            }
        }
    }

    float bvv[4];
#pragma unroll
    for (int j = 0; j < 4; ++j) bvv[j] = bu[ng + j];
#pragma unroll
    for (int p = 0; p < 2; ++p) {
        float2 c0 = unpack2(acc[p][0]);
        float2 c1 = unpack2(acc[p][1]);
        float2 c2 = unpack2(acc[p][2]);
        float2 c3 = unpack2(acc[p][3]);
        float4 o0 = { c0.x + bvv[0], c1.x + bvv[1], c2.x + bvv[2], c3.x + bvv[3] };
        float4 o1 = { c0.y + bvv[0], c1.y + bvv[1], c2.y + bvv[2], c3.y + bvv[3] };
        *(float4*)(out + (size_t)(m0 + mg + 2 * p)     * E + ng) = o0;
        *(float4*)(out + (size_t)(m0 + mg + 2 * p + 1) * E + ng) = o1;
    }
}

// ---------------------------------------------------------------------------
// Attention + alpha-entmax + value mix.
// 256 threads = 2 tokens; each score row owned by a LANE PAIR (32 cols each).
// Pair reductions via shfl_xor(.,1). f32x2 packed scores & value mix.
// ---------------------------------------------------------------------------
__global__ void __launch_bounds__(256, 2)
attn_kernel(const float* __restrict__ alpha_p)
{
    __shared__ __align__(16) float ks[2][HE];
    __shared__ __align__(16) float vs[2][HE];

    const int t    = threadIdx.x;
    const int tl   = t >> 7;        // token within CTA
    const int rr   = (t >> 1) & 63; // score row
    const int half = t & 1;         // which 32 columns
    const int base = blockIdx.x * 2;
    const size_t token = (size_t)(base + tl);

    // cooperative load of k,v for 2 tokens (256 float4 each array)
    ((float4*)ks)[t] = ((const float4*)(g_k + (size_t)base * HE))[t];
    ((float4*)vs)[t] = ((const float4*)(g_v + (size_t)base * HE))[t];

    const float alpha = *alpha_p;
    const float am1 = alpha - 1.0f;
    const float inv = 1.0f / am1;
    const float qscale = am1 * 0.125f;   // fold am1 * (1/sqrt(64)) into q

    float qr[H];
#pragma unroll
    for (int h = 0; h < H; ++h)
        qr[h] = g_q[token * HE + h * 64 + rr] * qscale;

    __syncthreads();

    // packed score accumulation: s2[u] holds cols (half*32+2u, +2u+1)
    ull s2[16];
#pragma unroll
    for (int u = 0; u < 16; ++u) s2[u] = 0ull;
#pragma unroll
    for (int h = 0; h < H; ++h) {
        const ull qh2 = pack2(qr[h], qr[h]);
        const ull* kp = (const ull*)&ks[tl][h * 64 + half * 32];
#pragma unroll
        for (int u = 0; u < 16; ++u)
            s2[u] = ffma2(qh2, kp[u], s2[u]);
    }
    float s[32];
#pragma unroll
    for (int u = 0; u < 16; ++u) {
        float2 f = unpack2(s2[u]);
        s[2 * u] = f.x; s[2 * u + 1] = f.y;
    }

    float mx = s[0];
#pragma unroll
    for (int j = 1; j < 32; ++j) mx = fmaxf(mx, s[j]);
    mx = fmaxf(mx, __shfl_xor_sync(0xffffffffu, mx, 1));

    if (fabsf(inv - 2.0f) < 1e-4f) {
        // alpha = 1.5: p(z) = relu(z)^2. Newton from below + exact quadratic.
        float tau = mx - 1.0f;
        const float tau_hi = mx - 0.125f;
#pragma unroll 1
        for (int it = 0; it < 6; ++it) {
            float S1 = 0.f, S2 = 0.f;
#pragma unroll
            for (int j = 0; j < 32; ++j) {
                float z = fmaxf(s[j] - tau, 0.0f);
                S1 += z; S2 = fmaf(z, z, S2);
            }
            S1 += __shfl_xor_sync(0xffffffffu, S1, 1);
            S2 += __shfl_xor_sync(0xffffffffu, S2, 1);
            tau = fminf(tau + __fdividef(S2 - 1.0f, 2.0f * S1), tau_hi);
        }
        // exact solve: cnt*tau^2 - 2*S1*tau + (S2-1) = 0 on active set
        float s1 = 0.f, sq = 0.f, cnt = 0.f;
#pragma unroll
        for (int j = 0; j < 32; ++j) {
            float z = s[j] - tau;
            float m = fmaxf(z, 0.0f);
            s1 += m; sq = fmaf(m, m, sq);
            cnt += (z > 0.0f) ? 1.0f : 0.0f;
        }
        s1  += __shfl_xor_sync(0xffffffffu, s1, 1);
        sq  += __shfl_xor_sync(0xffffffffu, sq, 1);
        cnt += __shfl_xor_sync(0xffffffffu, cnt, 1);
        float S1 = fmaf(tau, cnt, s1);
        float S2 = sq + 2.0f * tau * s1 + tau * tau * cnt;
        float disc = fmaxf(fmaf(-cnt, S2 - 1.0f, S1 * S1), 0.0f);
        tau = __fdividef(S1 - sqrtf(disc), cnt);

        float sum = 0.f;
#pragma unroll
        for (int j = 0; j < 32; ++j) {
            float m = fmaxf(s[j] - tau, 0.0f);
            s[j] = m * m;
            sum += s[j];
        }
        sum += __shfl_xor_sync(0xffffffffu, sum, 1);
        float rn = __fdividef(1.0f, sum);
#pragma unroll
        for (int j = 0; j < 32; ++j) s[j] *= rn;
    } else {
        // generic alpha: faithful 50-iter bisection with pair reductions
        float tau_lo = mx - 1.0f;
        float dm = (mx - __powf(1.0f / 64.0f, am1)) - tau_lo;
        float part = 0.f;
#pragma unroll
        for (int j = 0; j < 32; ++j) {
            float z = s[j] - tau_lo;
            if (z > 0.0f) part += __powf(fmaxf(z, 1e-30f), inv);
        }
        part += __shfl_xor_sync(0xffffffffu, part, 1);
        const float f_lo = part - 1.0f;
        float tau_m = tau_lo;
#pragma unroll 1
        for (int it = 0; it < 50; ++it) {
            dm *= 0.5f;
            tau_m = tau_lo + dm;
            float pm = 0.f;
#pragma unroll
            for (int j = 0; j < 32; ++j) {
                float z = s[j] - tau_m;
                if (z > 0.0f) pm += __powf(fmaxf(z, 1e-30f), inv);
            }
            pm += __shfl_xor_sync(0xffffffffu, pm, 1);
            if ((pm - 1.0f) * f_lo >= 0.0f) tau_lo = tau_m;
        }
        float sum = 0.f;
#pragma unroll
        for (int j = 0; j < 32; ++j) {
            float z = s[j] - tau_m;
            s[j] = (z > 0.0f) ? __powf(fmaxf(z, 1e-30f), inv) : 0.0f;
            sum += s[j];
        }
        sum += __shfl_xor_sync(0xffffffffu, sum, 1);
        float rn = __fdividef(1.0f, sum);
#pragma unroll
        for (int j = 0; j < 32; ++j) s[j] *= rn;
    }

    // value mix: res[h][rr] = sum_j att[rr][j] * v[h][j]   (packed, pair-reduced)
    ull att2[16];
#pragma unroll
    for (int u = 0; u < 16; ++u) att2[u] = pack2(s[2 * u], s[2 * u + 1]);
#pragma unroll
    for (int h = 0; h < H; ++h) {
        ull racc = 0ull;
        const ull* vp = (const ull*)&vs[tl][h * 64 + half * 32];
#pragma unroll
        for (int u = 0; u < 16; ++u)
            racc = ffma2(att2[u], vp[u], racc);
        float2 f = unpack2(racc);
        float rh = f.x + f.y;
        rh += __shfl_xor_sync(0xffffffffu, rh, 1);
        if (half == 0)
            g_res[token * HE + h * 64 + rr] = rh;
    }
}

// ---------------------------------------------------------------------------
extern "C" void kernel_launch(void* const* d_in, const int* in_sizes, int n_in,
                              void* d_out, int out_size)
{
    const float* x     = (const float*)d_in[0];
    const float* alpha = (const float*)d_in[1];
    const float* Wk    = (const float*)d_in[2];
    const float* bk    = (const float*)d_in[3];
    const float* Wq    = (const float*)d_in[4];
    const float* bq    = (const float*)d_in[5];
    const float* Wv    = (const float*)d_in[6];
    const float* bv    = (const float*)d_in[7];
    const float* Wu    = (const float*)d_in[8];
    const float* bu    = (const float*)d_in[9];

    const int tokens = in_sizes[0] / E;   // 16384

    qkv_gemm<<<dim3(24, tokens / 128), 256>>>(x, Wq, bq, Wk, bk, Wv, bv);
    attn_kernel<<<tokens / 2, 256>>>(alpha);
    out_gemm<<<tokens / 64, 256>>>(Wu, bu, (float*)d_out);
}

// round 4
// speedup vs baseline: 1.4888x; 1.1891x over previous
#include <cuda_runtime.h>

#define E 64
#define H 8
#define HE 512
#define MAX_TOKENS 16384

typedef unsigned long long ull;

__device__ __forceinline__ ull pack2(float lo, float hi) {
    ull r; asm("mov.b64 %0, {%1, %2};" : "=l"(r) : "f"(lo), "f"(hi)); return r;
}
__device__ __forceinline__ float2 unpack2(ull v) {
    float2 f; asm("mov.b64 {%0, %1}, %2;" : "=f"(f.x), "=f"(f.y) : "l"(v)); return f;
}
__device__ __forceinline__ ull ffma2(ull a, ull b, ull c) {
    ull d; asm("fma.rn.f32x2 %0, %1, %2, %3;" : "=l"(d) : "l"(a), "l"(b), "l"(c)); return d;
}

// scratch (device globals: no cudaMalloc allowed)
__device__ __align__(16) float g_q[MAX_TOKENS * HE];
__device__ __align__(16) float g_k[MAX_TOKENS * HE];
__device__ __align__(16) float g_v[MAX_TOKENS * HE];
__device__ __align__(16) float g_res[MAX_TOKENS * HE];

// ---------------------------------------------------------------------------
// Fused QKV GEMM.  O[m][n] = sum_k x[m][k] * W[n][k] + b[n]
// BM=128, BN=128, BK=32, 256 threads, 8x8 micro-tile (m packed in f32x2).
// grid: (12, tokens/128); blockIdx.x: widx = x>>2, n-block = x&3.
// ---------------------------------------------------------------------------
__global__ void __launch_bounds__(256, 2)
qkv_gemm(const float* __restrict__ x,
         const float* __restrict__ Wq, const float* __restrict__ bq,
         const float* __restrict__ Wk, const float* __restrict__ bk,
         const float* __restrict__ Wv, const float* __restrict__ bv)
{
    __shared__ __align__(16) float As[32][132];
    __shared__ __align__(16) float Bs[32][132];

    const int t    = threadIdx.x;
    const int m0   = blockIdx.y * 128;
    const int nblk = blockIdx.x;           // 0..11
    const int widx = nblk >> 2;
    const int n0   = (nblk & 3) * 128;

    const float* W    = (widx == 0) ? Wq : (widx == 1) ? Wk : Wv;
    const float* bias = (widx == 0) ? bq : (widx == 1) ? bk : bv;
    float* O          = (widx == 0) ? g_q : (widx == 1) ? g_k : g_v;

    const int my = (t >> 4) * 8;   // 8 m rows (4 f32x2 pairs)
    const int nx = (t & 15) * 8;   // 8 n cols

    ull acc[4][8];
#pragma unroll
    for (int p = 0; p < 4; ++p)
#pragma unroll
        for (int j = 0; j < 8; ++j) acc[p][j] = 0ull;

    const int lrow = t >> 1, lseg = t & 1;

    for (int kc = 0; kc < E; kc += 32) {
        __syncthreads();
        {   // A tile: 128 rows x 32 k (k-major)
            const float4* src = (const float4*)(x + (size_t)(m0 + lrow) * E + kc + lseg * 16);
#pragma unroll
            for (int i = 0; i < 4; ++i) {
                float4 v = src[i];
                int k = lseg * 16 + i * 4;
                As[k + 0][lrow] = v.x; As[k + 1][lrow] = v.y;
                As[k + 2][lrow] = v.z; As[k + 3][lrow] = v.w;
            }
        }
        {   // B tile: 128 rows x 32 k
            const float4* src = (const float4*)(W + (size_t)(n0 + lrow) * E + kc + lseg * 16);
#pragma unroll
            for (int i = 0; i < 4; ++i) {
                float4 v = src[i];
                int k = lseg * 16 + i * 4;
                Bs[k + 0][lrow] = v.x; Bs[k + 1][lrow] = v.y;
                Bs[k + 2][lrow] = v.z; Bs[k + 3][lrow] = v.w;
            }
        }
        __syncthreads();
#pragma unroll 8
        for (int k = 0; k < 32; ++k) {
            ull a[4];
            const ull* ap = (const ull*)&As[k][my];
            a[0] = ap[0]; a[1] = ap[1]; a[2] = ap[2]; a[3] = ap[3];
            float bf[8];
            *(float4*)&bf[0] = *(const float4*)&Bs[k][nx];
            *(float4*)&bf[4] = *(const float4*)&Bs[k][nx + 4];
#pragma unroll
            for (int j = 0; j < 8; ++j) {
                ull b2 = pack2(bf[j], bf[j]);
#pragma unroll
                for (int p = 0; p < 4; ++p)
                    acc[p][j] = ffma2(a[p], b2, acc[p][j]);
            }
        }
    }

    float bvv[8];
#pragma unroll
    for (int j = 0; j < 8; ++j) bvv[j] = bias[n0 + nx + j];
#pragma unroll
    for (int p = 0; p < 4; ++p) {
        float2 c[8];
#pragma unroll
        for (int j = 0; j < 8; ++j) c[j] = unpack2(acc[p][j]);
        float4 o0a = { c[0].x + bvv[0], c[1].x + bvv[1], c[2].x + bvv[2], c[3].x + bvv[3] };
        float4 o0b = { c[4].x + bvv[4], c[5].x + bvv[5], c[6].x + bvv[6], c[7].x + bvv[7] };
        float4 o1a = { c[0].y + bvv[0], c[1].y + bvv[1], c[2].y + bvv[2], c[3].y + bvv[3] };
        float4 o1b = { c[4].y + bvv[4], c[5].y + bvv[5], c[6].y + bvv[6], c[7].y + bvv[7] };
        float* r0 = O + (size_t)(m0 + my + 2 * p)     * HE + n0 + nx;
        float* r1 = O + (size_t)(m0 + my + 2 * p + 1) * HE + n0 + nx;
        *(float4*)(r0)     = o0a; *(float4*)(r0 + 4) = o0b;
        *(float4*)(r1)     = o1a; *(float4*)(r1 + 4) = o1b;
    }
}

// ---------------------------------------------------------------------------
// Output GEMM: out[m][n] = sum_k g_res[m][k] * Wu[n][k] + bu[n]
// BM=64, BN=64, BK=32, 256 threads, 4x4 micro-tile, f32x2 packed.
// ---------------------------------------------------------------------------
__global__ void __launch_bounds__(256)
out_gemm(const float* __restrict__ Wu, const float* __restrict__ bu,
         float* __restrict__ out)
{
    __shared__ __align__(16) float As[32][68];
    __shared__ __align__(16) float Bs[32][68];

    const int t  = threadIdx.x;
    const int m0 = blockIdx.x * 64;
    const int mg = (t >> 4) * 4;
    const int ng = (t & 15) * 4;

    ull acc[2][4];
#pragma unroll
    for (int p = 0; p < 2; ++p)
#pragma unroll
        for (int j = 0; j < 4; ++j) acc[p][j] = 0ull;

    for (int kc = 0; kc < HE; kc += 32) {
        __syncthreads();
        {
            const int row = t >> 2, seg = t & 3;
            const float4* src = (const float4*)(g_res + (size_t)(m0 + row) * HE + kc + seg * 8);
#pragma unroll
            for (int i = 0; i < 2; ++i) {
                float4 v = src[i];
                int k = seg * 8 + i * 4;
                As[k + 0][row] = v.x; As[k + 1][row] = v.y;
                As[k + 2][row] = v.z; As[k + 3][row] = v.w;
            }
        }
        {
            const int row = t >> 2, seg = t & 3;
            const float4* src = (const float4*)(Wu + (size_t)row * HE + kc + seg * 8);
#pragma unroll
            for (int i = 0; i < 2; ++i) {
                float4 v = src[i];
                int k = seg * 8 + i * 4;
                Bs[k + 0][row] = v.x; Bs[k + 1][row] = v.y;
                Bs[k + 2][row] = v.z; Bs[k + 3][row] = v.w;
            }
        }
        __syncthreads();
#pragma unroll 8
        for (int k = 0; k < 32; ++k) {
            ull a0 = *(const ull*)&As[k][mg + 0];
            ull a1 = *(const ull*)&As[k][mg + 2];
            float4 b = *(const float4*)&Bs[k][ng];
            ull b2[4] = { pack2(b.x, b.x), pack2(b.y, b.y),
                          pack2(b.z, b.z), pack2(b.w, b.w) };
#pragma unroll
            for (int j = 0; j < 4; ++j) {
                acc[0][j] = ffma2(a0, b2[j], acc[0][j]);
                acc[1][j] = ffma2(a1, b2[j], acc[1][j]);
            }
        }
    }

    float bvv[4];
#pragma unroll
    for (int j = 0; j < 4; ++j) bvv[j] = bu[ng + j];
#pragma unroll
    for (int p = 0; p < 2; ++p) {
        float2 c0 = unpack2(acc[p][0]);
        float2 c1 = unpack2(acc[p][1]);
        float2 c2 = unpack2(acc[p][2]);
        float2 c3 = unpack2(acc[p][3]);
        float4 o0 = { c0.x + bvv[0], c1.x + bvv[1], c2.x + bvv[2], c3.x + bvv[3] };
        float4 o1 = { c0.y + bvv[0], c1.y + bvv[1], c2.y + bvv[2], c3.y + bvv[3] };
        *(float4*)(out + (size_t)(m0 + mg + 2 * p)     * E + ng) = o0;
        *(float4*)(out + (size_t)(m0 + mg + 2 * p + 1) * E + ng) = o1;
    }
}

// ---------------------------------------------------------------------------
// Attention + alpha-entmax + value mix.
// 256 threads = 2 tokens; row owned by a LANE PAIR (32 cols each).
// k/v stored half-interleaved at 16B granularity: every warp LDS.128 touches
// exactly 2 distinct 16B words (broadcast, conflict-free, 1 wavefront).
// ---------------------------------------------------------------------------
__global__ void __launch_bounds__(256, 3)
attn_kernel(const float* __restrict__ alpha_p)
{
    // [tl][h][g][8]: floats {cols 4g..4g+3, cols 32+4g..32+4g+3}
    __shared__ __align__(16) float ksw[2][8][8][8];
    __shared__ __align__(16) float vsw[2][8][8][8];

    const int t    = threadIdx.x;
    const int tl   = t >> 7;        // token within CTA
    const int rr   = (t >> 1) & 63; // score row
    const int half = t & 1;         // which 32 columns
    const int base = blockIdx.x * 2;
    const size_t token = (size_t)(base + tl);

    // cooperative load with half-interleaving
    {
        const float4 vk = ((const float4*)(g_k + (size_t)base * HE))[t];
        const float4 vv = ((const float4*)(g_v + (size_t)base * HE))[t];
        const int th = t >> 4;      // tl*8 + h
        const int c  = t & 15;      // float4 within the 64-wide head row
        const int g  = c & 7;
        const int hh = c >> 3;      // which half this float4 belongs to
        float* kd = &ksw[0][0][0][0] + th * 64 + g * 8 + hh * 4;
        float* vd = &vsw[0][0][0][0] + th * 64 + g * 8 + hh * 4;
        *(float4*)kd = vk;
        *(float4*)vd = vv;
    }

    const float alpha = *alpha_p;
    const float am1 = alpha - 1.0f;
    const float inv = 1.0f / am1;
    const float qscale = am1 * 0.125f;   // fold am1 * (1/sqrt(64)) into q

    float qr[H];
#pragma unroll
    for (int h = 0; h < H; ++h)
        qr[h] = g_q[token * HE + h * 64 + rr] * qscale;

    __syncthreads();

    // packed score accumulation: s2[2g+d] holds cols (half*32+4g+2d, +1)
    ull s2[16];
#pragma unroll
    for (int u = 0; u < 16; ++u) s2[u] = 0ull;
#pragma unroll
    for (int h = 0; h < H; ++h) {
        const ull qh2 = pack2(qr[h], qr[h]);
        const ulonglong2* bp = (const ulonglong2*)&ksw[tl][h][0][0];
#pragma unroll
        for (int g = 0; g < 8; ++g) {
            ulonglong2 kk = bp[2 * g + half];
            s2[2 * g]     = ffma2(qh2, kk.x, s2[2 * g]);
            s2[2 * g + 1] = ffma2(qh2, kk.y, s2[2 * g + 1]);
        }
    }
    float s[32];
#pragma unroll
    for (int u = 0; u < 16; ++u) {
        float2 f = unpack2(s2[u]);
        s[2 * u] = f.x; s[2 * u + 1] = f.y;
    }

    float mx = s[0];
#pragma unroll
    for (int j = 1; j < 32; ++j) mx = fmaxf(mx, s[j]);
    mx = fmaxf(mx, __shfl_xor_sync(0xffffffffu, mx, 1));

    if (fabsf(inv - 2.0f) < 1e-4f) {
        // alpha = 1.5: p(z) = relu(z)^2. Newton from below + exact quadratic.
        float tau = mx - 1.0f;
        const float tau_hi = mx - 0.125f;
#pragma unroll 1
        for (int it = 0; it < 5; ++it) {
            float S1 = 0.f, S2 = 0.f;
#pragma unroll
            for (int j = 0; j < 32; ++j) {
                float z = fmaxf(s[j] - tau, 0.0f);
                S1 += z; S2 = fmaf(z, z, S2);
            }
            S1 += __shfl_xor_sync(0xffffffffu, S1, 1);
            S2 += __shfl_xor_sync(0xffffffffu, S2, 1);
            tau = fminf(tau + __fdividef(S2 - 1.0f, 2.0f * S1), tau_hi);
        }
        // exact solve: cnt*tau^2 - 2*S1*tau + (S2-1) = 0 on active set
        float s1 = 0.f, sq = 0.f, cnt = 0.f;
#pragma unroll
        for (int j = 0; j < 32; ++j) {
            float z = s[j] - tau;
            float m = fmaxf(z, 0.0f);
            s1 += m; sq = fmaf(m, m, sq);
            cnt += (z > 0.0f) ? 1.0f : 0.0f;
        }
        s1  += __shfl_xor_sync(0xffffffffu, s1, 1);
        sq  += __shfl_xor_sync(0xffffffffu, sq, 1);
        cnt += __shfl_xor_sync(0xffffffffu, cnt, 1);
        float S1 = fmaf(tau, cnt, s1);
        float S2 = sq + 2.0f * tau * s1 + tau * tau * cnt;
        float disc = fmaxf(fmaf(-cnt, S2 - 1.0f, S1 * S1), 0.0f);
        tau = __fdividef(S1 - sqrtf(disc), cnt);

        float sum = 0.f;
#pragma unroll
        for (int j = 0; j < 32; ++j) {
            float m = fmaxf(s[j] - tau, 0.0f);
            s[j] = m * m;
            sum += s[j];
        }
        sum += __shfl_xor_sync(0xffffffffu, sum, 1);
        float rn = __fdividef(1.0f, sum);
#pragma unroll
        for (int j = 0; j < 32; ++j) s[j] *= rn;
    } else {
        // generic alpha: faithful 50-iter bisection with pair reductions
        float tau_lo = mx - 1.0f;
        float dm = (mx - __powf(1.0f / 64.0f, am1)) - tau_lo;
        float part = 0.f;
#pragma unroll
        for (int j = 0; j < 32; ++j) {
            float z = s[j] - tau_lo;
            if (z > 0.0f) part += __powf(fmaxf(z, 1e-30f), inv);
        }
        part += __shfl_xor_sync(0xffffffffu, part, 1);
        const float f_lo = part - 1.0f;
        float tau_m = tau_lo;
#pragma unroll 1
        for (int it = 0; it < 50; ++it) {
            dm *= 0.5f;
            tau_m = tau_lo + dm;
            float pm = 0.f;
#pragma unroll
            for (int j = 0; j < 32; ++j) {
                float z = s[j] - tau_m;
                if (z > 0.0f) pm += __powf(fmaxf(z, 1e-30f), inv);
            }
            pm += __shfl_xor_sync(0xffffffffu, pm, 1);
            if ((pm - 1.0f) * f_lo >= 0.0f) tau_lo = tau_m;
        }
        float sum = 0.f;
#pragma unroll
        for (int j = 0; j < 32; ++j) {
            float z = s[j] - tau_m;
            s[j] = (z > 0.0f) ? __powf(fmaxf(z, 1e-30f), inv) : 0.0f;
            sum += s[j];
        }
        sum += __shfl_xor_sync(0xffffffffu, sum, 1);
        float rn = __fdividef(1.0f, sum);
#pragma unroll
        for (int j = 0; j < 32; ++j) s[j] *= rn;
    }

    // value mix: res[h][rr] = sum_j att[rr][j] * v[h][j]
    ull att2[16];
#pragma unroll
    for (int u = 0; u < 16; ++u) att2[u] = pack2(s[2 * u], s[2 * u + 1]);
#pragma unroll
    for (int h = 0; h < H; ++h) {
        ull racc = 0ull;
        const ulonglong2* bp = (const ulonglong2*)&vsw[tl][h][0][0];
#pragma unroll
        for (int g = 0; g < 8; ++g) {
            ulonglong2 vv = bp[2 * g + half];
            racc = ffma2(att2[2 * g],     vv.x, racc);
            racc = ffma2(att2[2 * g + 1], vv.y, racc);
        }
        float2 f = unpack2(racc);
        float rh = f.x + f.y;
        rh += __shfl_xor_sync(0xffffffffu, rh, 1);
        if (half == (h & 1))
            g_res[token * HE + h * 64 + rr] = rh;
    }
}

// ---------------------------------------------------------------------------
extern "C" void kernel_launch(void* const* d_in, const int* in_sizes, int n_in,
                              void* d_out, int out_size)
{
    const float* x     = (const float*)d_in[0];
    const float* alpha = (const float*)d_in[1];
    const float* Wk    = (const float*)d_in[2];
    const float* bk    = (const float*)d_in[3];
    const float* Wq    = (const float*)d_in[4];
    const float* bq    = (const float*)d_in[5];
    const float* Wv    = (const float*)d_in[6];
    const float* bv    = (const float*)d_in[7];
    const float* Wu    = (const float*)d_in[8];
    const float* bu    = (const float*)d_in[9];

    const int tokens = in_sizes[0] / E;   // 16384

    qkv_gemm<<<dim3(12, tokens / 128), 256>>>(x, Wq, bq, Wk, bk, Wv, bv);
    attn_kernel<<<tokens / 2, 256>>>(alpha);
    out_gemm<<<tokens / 64, 256>>>(Wu, bu, (float*)d_out);
}

// round 6
// speedup vs baseline: 1.4966x; 1.0052x over previous
#include <cuda_runtime.h>

#define E 64
#define H 8
#define HE 512
#define MAX_TOKENS 16384

typedef unsigned long long ull;

__device__ __forceinline__ ull pack2(float lo, float hi) {
    ull r; asm("mov.b64 %0, {%1, %2};" : "=l"(r) : "f"(lo), "f"(hi)); return r;
}
__device__ __forceinline__ float2 unpack2(ull v) {
    float2 f; asm("mov.b64 {%0, %1}, %2;" : "=f"(f.x), "=f"(f.y) : "l"(v)); return f;
}
__device__ __forceinline__ ull ffma2(ull a, ull b, ull c) {
    ull d; asm("fma.rn.f32x2 %0, %1, %2, %3;" : "=l"(d) : "l"(a), "l"(b), "l"(c)); return d;
}

// scratch (device globals: no cudaMalloc allowed)
__device__ __align__(16) float g_q[MAX_TOKENS * HE];
__device__ __align__(16) float g_k[MAX_TOKENS * HE];
__device__ __align__(16) float g_v[MAX_TOKENS * HE];
__device__ __align__(16) float g_res[MAX_TOKENS * HE];

// ---------------------------------------------------------------------------
// Fused QKV GEMM.  O[m][n] = sum_k x[m][k] * W[n][k] + b[n]
// BM=128, BN=128, K=64 staged in smem ONCE, 256 threads, 8x8 f32x2 micro-tile.
// grid: (12, tokens/128); widx = blockIdx.x>>2, n-block = blockIdx.x&3.
// ---------------------------------------------------------------------------
__global__ void __launch_bounds__(256, 2)
qkv_gemm(const float* __restrict__ x,
         const float* __restrict__ Wq, const float* __restrict__ bq,
         const float* __restrict__ Wk, const float* __restrict__ bk,
         const float* __restrict__ Wv, const float* __restrict__ bv)
{
    extern __shared__ __align__(16) float smem[];
    float (*As)[132] = (float (*)[132])smem;             // [64][132]
    float (*Bs)[132] = (float (*)[132])(smem + 64 * 132);

    const int t    = threadIdx.x;
    const int m0   = blockIdx.y * 128;
    const int nblk = blockIdx.x;           // 0..11
    const int widx = nblk >> 2;
    const int n0   = (nblk & 3) * 128;

    const float* W    = (widx == 0) ? Wq : (widx == 1) ? Wk : Wv;
    const float* bias = (widx == 0) ? bq : (widx == 1) ? bk : bv;
    float* O          = (widx == 0) ? g_q : (widx == 1) ? g_k : g_v;

    const int my = (t >> 4) * 8;   // 8 m rows (4 f32x2 pairs)
    const int nx = (t & 15) * 8;   // 8 n cols

    const int lrow = t >> 1, lseg = t & 1;

    // stage full K=64 tiles (k-major)
#pragma unroll
    for (int half = 0; half < 2; ++half) {
        const float4* srcA = (const float4*)(x + (size_t)(m0 + lrow) * E + half * 32 + lseg * 16);
        const float4* srcB = (const float4*)(W + (size_t)(n0 + lrow) * E + half * 32 + lseg * 16);
#pragma unroll
        for (int i = 0; i < 4; ++i) {
            float4 va = srcA[i];
            float4 vb = srcB[i];
            int k = half * 32 + lseg * 16 + i * 4;
            As[k + 0][lrow] = va.x; As[k + 1][lrow] = va.y;
            As[k + 2][lrow] = va.z; As[k + 3][lrow] = va.w;
            Bs[k + 0][lrow] = vb.x; Bs[k + 1][lrow] = vb.y;
            Bs[k + 2][lrow] = vb.z; Bs[k + 3][lrow] = vb.w;
        }
    }
    __syncthreads();

    ull acc[4][8];
#pragma unroll
    for (int p = 0; p < 4; ++p)
#pragma unroll
        for (int j = 0; j < 8; ++j) acc[p][j] = 0ull;

#pragma unroll 8
    for (int k = 0; k < 64; ++k) {
        ull a[4];
        const ull* ap = (const ull*)&As[k][my];
        a[0] = ap[0]; a[1] = ap[1]; a[2] = ap[2]; a[3] = ap[3];
        float bf[8];
        *(float4*)&bf[0] = *(const float4*)&Bs[k][nx];
        *(float4*)&bf[4] = *(const float4*)&Bs[k][nx + 4];
#pragma unroll
        for (int j = 0; j < 8; ++j) {
            ull b2 = pack2(bf[j], bf[j]);
#pragma unroll
            for (int p = 0; p < 4; ++p)
                acc[p][j] = ffma2(a[p], b2, acc[p][j]);
        }
    }

    float bvv[8];
#pragma unroll
    for (int j = 0; j < 8; ++j) bvv[j] = bias[n0 + nx + j];
#pragma unroll
    for (int p = 0; p < 4; ++p) {
        float2 c[8];
#pragma unroll
        for (int j = 0; j < 8; ++j) c[j] = unpack2(acc[p][j]);
        float4 o0a = { c[0].x + bvv[0], c[1].x + bvv[1], c[2].x + bvv[2], c[3].x + bvv[3] };
        float4 o0b = { c[4].x + bvv[4], c[5].x + bvv[5], c[6].x + bvv[6], c[7].x + bvv[7] };
        float4 o1a = { c[0].y + bvv[0], c[1].y + bvv[1], c[2].y + bvv[2], c[3].y + bvv[3] };
        float4 o1b = { c[4].y + bvv[4], c[5].y + bvv[5], c[6].y + bvv[6], c[7].y + bvv[7] };
        float* r0 = O + (size_t)(m0 + my + 2 * p)     * HE + n0 + nx;
        float* r1 = O + (size_t)(m0 + my + 2 * p + 1) * HE + n0 + nx;
        *(float4*)(r0)     = o0a; *(float4*)(r0 + 4) = o0b;
        *(float4*)(r1)     = o1a; *(float4*)(r1 + 4) = o1b;
    }
}

// ---------------------------------------------------------------------------
// Output GEMM: out[m][n] = sum_k g_res[m][k] * Wu[n][k] + bu[n]
// BM=128, BN=64 (full N), BK=64, 256 threads, 8x4 f32x2 micro-tile.
// ---------------------------------------------------------------------------
__global__ void __launch_bounds__(256, 2)
out_gemm(const float* __restrict__ Wu, const float* __restrict__ bu,
         float* __restrict__ out)
{
    extern __shared__ __align__(16) float smem[];
    float (*As)[132] = (float (*)[132])smem;             // [64][132]
    float (*Bs)[68]  = (float (*)[68])(smem + 64 * 132); // [64][68]

    const int t  = threadIdx.x;
    const int m0 = blockIdx.x * 128;
    const int my = (t >> 4) * 8;   // 8 m rows
    const int ng = (t & 15) * 4;   // 4 n cols

    ull acc[4][4];
#pragma unroll
    for (int p = 0; p < 4; ++p)
#pragma unroll
        for (int j = 0; j < 4; ++j) acc[p][j] = 0ull;

    const int arow = t >> 1, aseg = t & 1;
    const int brow = t >> 2, bseg = t & 3;

    for (int kc = 0; kc < HE; kc += 64) {
        __syncthreads();
        {   // A tile: 128 rows x 64 k
            const float4* src = (const float4*)(g_res + (size_t)(m0 + arow) * HE + kc + aseg * 32);
#pragma unroll
            for (int i = 0; i < 8; ++i) {
                float4 v = src[i];
                int k = aseg * 32 + i * 4;
                As[k + 0][arow] = v.x; As[k + 1][arow] = v.y;
                As[k + 2][arow] = v.z; As[k + 3][arow] = v.w;
            }
        }
        {   // B tile: 64 rows x 64 k
            const float4* src = (const float4*)(Wu + (size_t)brow * HE + kc + bseg * 16);
#pragma unroll
            for (int i = 0; i < 4; ++i) {
                float4 v = src[i];
                int k = bseg * 16 + i * 4;
                Bs[k + 0][brow] = v.x; Bs[k + 1][brow] = v.y;
                Bs[k + 2][brow] = v.z; Bs[k + 3][brow] = v.w;
            }
        }
        __syncthreads();
#pragma unroll 8
        for (int k = 0; k < 64; ++k) {
            ull a[4];
            const ull* ap = (const ull*)&As[k][my];
            a[0] = ap[0]; a[1] = ap[1]; a[2] = ap[2]; a[3] = ap[3];
            float4 b = *(const float4*)&Bs[k][ng];
            ull b2[4] = { pack2(b.x, b.x), pack2(b.y, b.y),
                          pack2(b.z, b.z), pack2(b.w, b.w) };
#pragma unroll
            for (int j = 0; j < 4; ++j)
#pragma unroll
                for (int p = 0; p < 4; ++p)
                    acc[p][j] = ffma2(a[p], b2[j], acc[p][j]);
        }
    }

    float bvv[4];
#pragma unroll
    for (int j = 0; j < 4; ++j) bvv[j] = bu[ng + j];
#pragma unroll
    for (int p = 0; p < 4; ++p) {
        float2 c0 = unpack2(acc[p][0]);
        float2 c1 = unpack2(acc[p][1]);
        float2 c2 = unpack2(acc[p][2]);
        float2 c3 = unpack2(acc[p][3]);
        float4 o0 = { c0.x + bvv[0], c1.x + bvv[1], c2.x + bvv[2], c3.x + bvv[3] };
        float4 o1 = { c0.y + bvv[0], c1.y + bvv[1], c2.y + bvv[2], c3.y + bvv[3] };
        *(float4*)(out + (size_t)(m0 + my + 2 * p)     * E + ng) = o0;
        *(float4*)(out + (size_t)(m0 + my + 2 * p + 1) * E + ng) = o1;
    }
}

// ---------------------------------------------------------------------------
// Attention + alpha-entmax + value mix.
// 256 threads = 2 tokens; row owned by a LANE PAIR (32 cols each).
// k/v stored half-interleaved at 16B granularity: every warp LDS.128 touches
// exactly 2 distinct 16B words (broadcast, conflict-free, 1 wavefront).
// ---------------------------------------------------------------------------
__global__ void __launch_bounds__(256, 3)
attn_kernel(const float* __restrict__ alpha_p)
{
    // [tl][h][g][8]: floats {cols 4g..4g+3, cols 32+4g..32+4g+3}
    __shared__ __align__(16) float ksw[2][8][8][8];
    __shared__ __align__(16) float vsw[2][8][8][8];

    const int t    = threadIdx.x;
    const int tl   = t >> 7;        // token within CTA
    const int rr   = (t >> 1) & 63; // score row
    const int half = t & 1;         // which 32 columns
    const int base = blockIdx.x * 2;
    const size_t token = (size_t)(base + tl);

    // cooperative load with half-interleaving
    {
        const float4 vk = ((const float4*)(g_k + (size_t)base * HE))[t];
        const float4 vv = ((const float4*)(g_v + (size_t)base * HE))[t];
        const int th = t >> 4;      // tl*8 + h
        const int c  = t & 15;      // float4 within the 64-wide head row
        const int g  = c & 7;
        const int hh = c >> 3;      // which half this float4 belongs to
        float* kd = &ksw[0][0][0][0] + th * 64 + g * 8 + hh * 4;
        float* vd = &vsw[0][0][0][0] + th * 64 + g * 8 + hh * 4;
        *(float4*)kd = vk;
        *(float4*)vd = vv;
    }

    const float alpha = *alpha_p;
    const float am1 = alpha - 1.0f;
    const float inv = 1.0f / am1;
    const float qscale = am1 * 0.125f;   // fold am1 * (1/sqrt(64)) into q

    float qr[H];
#pragma unroll
    for (int h = 0; h < H; ++h)
        qr[h] = g_q[token * HE + h * 64 + rr] * qscale;

    __syncthreads();

    // packed score accumulation: s2[2g+d] holds cols (half*32+4g+2d, +1)
    ull s2[16];
#pragma unroll
    for (int u = 0; u < 16; ++u) s2[u] = 0ull;
#pragma unroll
    for (int h = 0; h < H; ++h) {
        const ull qh2 = pack2(qr[h], qr[h]);
        const ulonglong2* bp = (const ulonglong2*)&ksw[tl][h][0][0];
#pragma unroll
        for (int g = 0; g < 8; ++g) {
            ulonglong2 kk = bp[2 * g + half];
            s2[2 * g]     = ffma2(qh2, kk.x, s2[2 * g]);
            s2[2 * g + 1] = ffma2(qh2, kk.y, s2[2 * g + 1]);
        }
    }
    float s[32];
#pragma unroll
    for (int u = 0; u < 16; ++u) {
        float2 f = unpack2(s2[u]);
        s[2 * u] = f.x; s[2 * u + 1] = f.y;
    }

    float mx = s[0];
#pragma unroll
    for (int j = 1; j < 32; ++j) mx = fmaxf(mx, s[j]);
    mx = fmaxf(mx, __shfl_xor_sync(0xffffffffu, mx, 1));

    if (fabsf(inv - 2.0f) < 1e-4f) {
        // alpha = 1.5: p(z) = relu(z)^2. Newton from below + exact quadratic.
        float tau = mx - 1.0f;
        const float tau_hi = mx - 0.125f;
#pragma unroll 1
        for (int it = 0; it < 4; ++it) {
            float S1 = 0.f, S2 = 0.f;
#pragma unroll
            for (int j = 0; j < 32; ++j) {
                float z = fmaxf(s[j] - tau, 0.0f);
                S1 += z; S2 = fmaf(z, z, S2);
            }
            S1 += __shfl_xor_sync(0xffffffffu, S1, 1);
            S2 += __shfl_xor_sync(0xffffffffu, S2, 1);
            tau = fminf(tau + __fdividef(S2 - 1.0f, 2.0f * S1), tau_hi);
        }
        // exact solve: cnt*tau^2 - 2*S1*tau + (S2-1) = 0 on active set
        float s1 = 0.f, sq = 0.f, cnt = 0.f;
#pragma unroll
        for (int j = 0; j < 32; ++j) {
            float z = s[j] - tau;
            float m = fmaxf(z, 0.0f);
            s1 += m; sq = fmaf(m, m, sq);
            cnt += (z > 0.0f) ? 1.0f : 0.0f;
        }
        s1  += __shfl_xor_sync(0xffffffffu, s1, 1);
        sq  += __shfl_xor_sync(0xffffffffu, sq, 1);
        cnt += __shfl_xor_sync(0xffffffffu, cnt, 1);
        float S1 = fmaf(tau, cnt, s1);
        float S2 = sq + 2.0f * tau * s1 + tau * tau * cnt;
        float disc = fmaxf(fmaf(-cnt, S2 - 1.0f, S1 * S1), 0.0f);
        tau = __fdividef(S1 - sqrtf(disc), cnt);

        float sum = 0.f;
#pragma unroll
        for (int j = 0; j < 32; ++j) {
            float m = fmaxf(s[j] - tau, 0.0f);
            s[j] = m * m;
            sum += s[j];
        }
        sum += __shfl_xor_sync(0xffffffffu, sum, 1);
        float rn = __fdividef(1.0f, sum);
#pragma unroll
        for (int j = 0; j < 32; ++j) s[j] *= rn;
    } else {
        // generic alpha: faithful 50-iter bisection with pair reductions
        float tau_lo = mx - 1.0f;
        float dm = (mx - __powf(1.0f / 64.0f, am1)) - tau_lo;
        float part = 0.f;
#pragma unroll
        for (int j = 0; j < 32; ++j) {
            float z = s[j] - tau_lo;
            if (z > 0.0f) part += __powf(fmaxf(z, 1e-30f), inv);
        }
        part += __shfl_xor_sync(0xffffffffu, part, 1);
        const float f_lo = part - 1.0f;
        float tau_m = tau_lo;
#pragma unroll 1
        for (int it = 0; it < 50; ++it) {
            dm *= 0.5f;
            tau_m = tau_lo + dm;
            float pm = 0.f;
#pragma unroll
            for (int j = 0; j < 32; ++j) {
                float z = s[j] - tau_m;
                if (z > 0.0f) pm += __powf(fmaxf(z, 1e-30f), inv);
            }
            pm += __shfl_xor_sync(0xffffffffu, pm, 1);
            if ((pm - 1.0f) * f_lo >= 0.0f) tau_lo = tau_m;
        }
        float sum = 0.f;
#pragma unroll
        for (int j = 0; j < 32; ++j) {
            float z = s[j] - tau_m;
            s[j] = (z > 0.0f) ? __powf(fmaxf(z, 1e-30f), inv) : 0.0f;
            sum += s[j];
        }
        sum += __shfl_xor_sync(0xffffffffu, sum, 1);
        float rn = __fdividef(1.0f, sum);
#pragma unroll
        for (int j = 0; j < 32; ++j) s[j] *= rn;
    }

    // value mix: res[h][rr] = sum_j att[rr][j] * v[h][j]
    ull att2[16];
#pragma unroll
    for (int u = 0; u < 16; ++u) att2[u] = pack2(s[2 * u], s[2 * u + 1]);
#pragma unroll
    for (int h = 0; h < H; ++h) {
        ull racc = 0ull;
        const ulonglong2* bp = (const ulonglong2*)&vsw[tl][h][0][0];
#pragma unroll
        for (int g = 0; g < 8; ++g) {
            ulonglong2 vv = bp[2 * g + half];
            racc = ffma2(att2[2 * g],     vv.x, racc);
            racc = ffma2(att2[2 * g + 1], vv.y, racc);
        }
        float2 f = unpack2(racc);
        float rh = f.x + f.y;
        rh += __shfl_xor_sync(0xffffffffu, rh, 1);
        if (half == (h & 1))
            g_res[token * HE + h * 64 + rr] = rh;
    }
}

// ---------------------------------------------------------------------------
extern "C" void kernel_launch(void* const* d_in, const int* in_sizes, int n_in,
                              void* d_out, int out_size)
{
    const float* x     = (const float*)d_in[0];
    const float* alpha = (const float*)d_in[1];
    const float* Wk    = (const float*)d_in[2];
    const float* bk    = (const float*)d_in[3];
    const float* Wq    = (const float*)d_in[4];
    const float* bq    = (const float*)d_in[5];
    const float* Wv    = (const float*)d_in[6];
    const float* bv    = (const float*)d_in[7];
    const float* Wu    = (const float*)d_in[8];
    const float* bu    = (const float*)d_in[9];

    const int tokens = in_sizes[0] / E;   // 16384

    const int qkv_smem = 2 * 64 * 132 * sizeof(float);           // 67584
    const int out_smem = (64 * 132 + 64 * 68) * sizeof(float);   // 51200
    static int attr_done = 0;
    if (!attr_done) {
        cudaFuncSetAttribute(qkv_gemm, cudaFuncAttributeMaxDynamicSharedMemorySize, qkv_smem);
        cudaFuncSetAttribute(out_gemm, cudaFuncAttributeMaxDynamicSharedMemorySize, out_smem);
        attr_done = 1;
    }

    qkv_gemm<<<dim3(12, tokens / 128), 256, qkv_smem>>>(x, Wq, bq, Wk, bk, Wv, bv);
    attn_kernel<<<tokens / 2, 256>>>(alpha);
    out_gemm<<<tokens / 128, 256, out_smem>>>(Wu, bu, (float*)d_out);
}

// round 7
// speedup vs baseline: 1.6448x; 1.0990x over previous
#include <cuda_runtime.h>

#define E 64
#define H 8
#define HE 512
#define MAX_TOKENS 16384

typedef unsigned long long ull;

__device__ __forceinline__ ull pack2(float lo, float hi) {
    ull r; asm("mov.b64 %0, {%1, %2};" : "=l"(r) : "f"(lo), "f"(hi)); return r;
}
__device__ __forceinline__ float2 unpack2(ull v) {
    float2 f; asm("mov.b64 {%0, %1}, %2;" : "=f"(f.x), "=f"(f.y) : "l"(v)); return f;
}
__device__ __forceinline__ ull ffma2(ull a, ull b, ull c) {
    ull d; asm("fma.rn.f32x2 %0, %1, %2, %3;" : "=l"(d) : "l"(a), "l"(b), "l"(c)); return d;
}

// scratch (device globals: no cudaMalloc allowed)
__device__ __align__(16) float g_q[MAX_TOKENS * HE];
__device__ __align__(16) float g_k[MAX_TOKENS * HE];
__device__ __align__(16) float g_v[MAX_TOKENS * HE];
__device__ __align__(16) float g_res[MAX_TOKENS * HE];

// ---------------------------------------------------------------------------
// Fused QKV GEMM.  O[m][n] = sum_k x[m][k] * W[n][k] + b[n]
// BM=128, BN=128, K=64 staged once. 256 threads.
// Lane map: warp covers 8 m-groups x 4 n-groups (min smem traffic).
// A stored half-interleaved As[k][sub][G*4+pos] so each A LDS.128 hits
// 8 contiguous 16B chunks (1 wavefront). B natural k-major (1 wf/instr).
// ---------------------------------------------------------------------------
__global__ void __launch_bounds__(256, 2)
qkv_gemm(const float* __restrict__ x,
         const float* __restrict__ Wq, const float* __restrict__ bq,
         const float* __restrict__ Wk, const float* __restrict__ bk,
         const float* __restrict__ Wv, const float* __restrict__ bv)
{
    extern __shared__ __align__(16) float smem[];
    float (*As)[2][68] = (float (*)[2][68])smem;               // [64][2][68]
    float (*Bs)[132]   = (float (*)[132])(smem + 64 * 2 * 68); // [64][132]

    const int t    = threadIdx.x;
    const int lane = t & 31;
    const int w    = t >> 5;
    const int m0   = blockIdx.y * 128;
    const int nblk = blockIdx.x;           // 0..11
    const int widx = nblk >> 2;
    const int n0   = (nblk & 3) * 128;

    const float* W    = (widx == 0) ? Wq : (widx == 1) ? Wk : Wv;
    const float* bias = (widx == 0) ? bq : (widx == 1) ? bk : bv;
    float* O          = (widx == 0) ? g_q : (widx == 1) ? g_k : g_v;

    const int G  = (w & 1) * 8 + (lane >> 2);        // m-group 0..15
    const int my = G * 8;                            // 8 m rows
    const int nx = (w >> 1) * 32 + (lane & 3) * 8;   // 8 n cols

    const int lrow = t >> 1, lseg = t & 1;
    const int sg = lrow >> 3, ssub = (lrow >> 2) & 1, spos = lrow & 3;

    // stage full K=64 tiles
#pragma unroll
    for (int half = 0; half < 2; ++half) {
        const float4* srcA = (const float4*)(x + (size_t)(m0 + lrow) * E + half * 32 + lseg * 16);
        const float4* srcB = (const float4*)(W + (size_t)(n0 + lrow) * E + half * 32 + lseg * 16);
#pragma unroll
        for (int i = 0; i < 4; ++i) {
            float4 va = srcA[i];
            float4 vb = srcB[i];
            int k = half * 32 + lseg * 16 + i * 4;
            As[k + 0][ssub][sg * 4 + spos] = va.x;
            As[k + 1][ssub][sg * 4 + spos] = va.y;
            As[k + 2][ssub][sg * 4 + spos] = va.z;
            As[k + 3][ssub][sg * 4 + spos] = va.w;
            Bs[k + 0][lrow] = vb.x; Bs[k + 1][lrow] = vb.y;
            Bs[k + 2][lrow] = vb.z; Bs[k + 3][lrow] = vb.w;
        }
    }
    __syncthreads();

    ull acc[4][8];
#pragma unroll
    for (int p = 0; p < 4; ++p)
#pragma unroll
        for (int j = 0; j < 8; ++j) acc[p][j] = 0ull;

#pragma unroll 8
    for (int k = 0; k < 64; ++k) {
        ulonglong2 qa0 = *(const ulonglong2*)&As[k][0][G * 4];  // m+0..3
        ulonglong2 qa1 = *(const ulonglong2*)&As[k][1][G * 4];  // m+4..7
        ull a[4] = { qa0.x, qa0.y, qa1.x, qa1.y };
        float bf[8];
        *(float4*)&bf[0] = *(const float4*)&Bs[k][nx];
        *(float4*)&bf[4] = *(const float4*)&Bs[k][nx + 4];
#pragma unroll
        for (int j = 0; j < 8; ++j) {
            ull b2 = pack2(bf[j], bf[j]);
#pragma unroll
            for (int p = 0; p < 4; ++p)
                acc[p][j] = ffma2(a[p], b2, acc[p][j]);
        }
    }

    float bvv[8];
#pragma unroll
    for (int j = 0; j < 8; ++j) bvv[j] = bias[n0 + nx + j];
#pragma unroll
    for (int p = 0; p < 4; ++p) {
        float2 c[8];
#pragma unroll
        for (int j = 0; j < 8; ++j) c[j] = unpack2(acc[p][j]);
        float4 o0a = { c[0].x + bvv[0], c[1].x + bvv[1], c[2].x + bvv[2], c[3].x + bvv[3] };
        float4 o0b = { c[4].x + bvv[4], c[5].x + bvv[5], c[6].x + bvv[6], c[7].x + bvv[7] };
        float4 o1a = { c[0].y + bvv[0], c[1].y + bvv[1], c[2].y + bvv[2], c[3].y + bvv[3] };
        float4 o1b = { c[4].y + bvv[4], c[5].y + bvv[5], c[6].y + bvv[6], c[7].y + bvv[7] };
        float* r0 = O + (size_t)(m0 + my + 2 * p)     * HE + n0 + nx;
        float* r1 = O + (size_t)(m0 + my + 2 * p + 1) * HE + n0 + nx;
        *(float4*)(r0)     = o0a; *(float4*)(r0 + 4) = o0b;
        *(float4*)(r1)     = o1a; *(float4*)(r1 + 4) = o1b;
    }
}

// ---------------------------------------------------------------------------
// Output GEMM: out[m][n] = sum_k g_res[m][k] * Wu[n][k] + bu[n]
// BM=128, BN=64, BK=64, 256 threads, warp = 8 m-groups x 4 n-groups,
// A half-interleaved like qkv_gemm.
// ---------------------------------------------------------------------------
__global__ void __launch_bounds__(256, 3)
out_gemm(const float* __restrict__ Wu, const float* __restrict__ bu,
         float* __restrict__ out)
{
    extern __shared__ __align__(16) float smem[];
    float (*As)[2][68] = (float (*)[2][68])smem;               // [64][2][68]
    float (*Bs)[68]    = (float (*)[68])(smem + 64 * 2 * 68);  // [64][68]

    const int t    = threadIdx.x;
    const int lane = t & 31;
    const int w    = t >> 5;
    const int m0   = blockIdx.x * 128;

    const int G  = (w & 1) * 8 + (lane >> 2);        // m-group 0..15
    const int my = G * 8;
    const int nx = (w >> 1) * 16 + (lane & 3) * 4;   // 4 n cols

    ull acc[4][4];
#pragma unroll
    for (int p = 0; p < 4; ++p)
#pragma unroll
        for (int j = 0; j < 4; ++j) acc[p][j] = 0ull;

    const int arow = t >> 1, aseg = t & 1;
    const int sg = arow >> 3, ssub = (arow >> 2) & 1, spos = arow & 3;
    const int brow = t >> 2, bseg = t & 3;

    for (int kc = 0; kc < HE; kc += 64) {
        __syncthreads();
        {   // A tile: 128 rows x 64 k (half-interleaved)
            const float4* src = (const float4*)(g_res + (size_t)(m0 + arow) * HE + kc + aseg * 32);
#pragma unroll
            for (int i = 0; i < 8; ++i) {
                float4 v = src[i];
                int k = aseg * 32 + i * 4;
                As[k + 0][ssub][sg * 4 + spos] = v.x;
                As[k + 1][ssub][sg * 4 + spos] = v.y;
                As[k + 2][ssub][sg * 4 + spos] = v.z;
                As[k + 3][ssub][sg * 4 + spos] = v.w;
            }
        }
        {   // B tile: 64 rows x 64 k
            const float4* src = (const float4*)(Wu + (size_t)brow * HE + kc + bseg * 16);
#pragma unroll
            for (int i = 0; i < 4; ++i) {
                float4 v = src[i];
                int k = bseg * 16 + i * 4;
                Bs[k + 0][brow] = v.x; Bs[k + 1][brow] = v.y;
                Bs[k + 2][brow] = v.z; Bs[k + 3][brow] = v.w;
            }
        }
        __syncthreads();
#pragma unroll 8
        for (int k = 0; k < 64; ++k) {
            ulonglong2 qa0 = *(const ulonglong2*)&As[k][0][G * 4];
            ulonglong2 qa1 = *(const ulonglong2*)&As[k][1][G * 4];
            ull a[4] = { qa0.x, qa0.y, qa1.x, qa1.y };
            float4 b = *(const float4*)&Bs[k][nx];
            ull b2[4] = { pack2(b.x, b.x), pack2(b.y, b.y),
                          pack2(b.z, b.z), pack2(b.w, b.w) };
#pragma unroll
            for (int j = 0; j < 4; ++j)
#pragma unroll
                for (int p = 0; p < 4; ++p)
                    acc[p][j] = ffma2(a[p], b2[j], acc[p][j]);
        }
    }

    float bvv[4];
#pragma unroll
    for (int j = 0; j < 4; ++j) bvv[j] = bu[nx + j];
#pragma unroll
    for (int p = 0; p < 4; ++p) {
        float2 c0 = unpack2(acc[p][0]);
        float2 c1 = unpack2(acc[p][1]);
        float2 c2 = unpack2(acc[p][2]);
        float2 c3 = unpack2(acc[p][3]);
        float4 o0 = { c0.x + bvv[0], c1.x + bvv[1], c2.x + bvv[2], c3.x + bvv[3] };
        float4 o1 = { c0.y + bvv[0], c1.y + bvv[1], c2.y + bvv[2], c3.y + bvv[3] };
        *(float4*)(out + (size_t)(m0 + my + 2 * p)     * E + nx) = o0;
        *(float4*)(out + (size_t)(m0 + my + 2 * p + 1) * E + nx) = o1;
    }
}

// ---------------------------------------------------------------------------
// Attention + alpha-entmax + value mix.  (unchanged from round 6)
// ---------------------------------------------------------------------------
__global__ void __launch_bounds__(256, 3)
attn_kernel(const float* __restrict__ alpha_p)
{
    // [tl][h][g][8]: floats {cols 4g..4g+3, cols 32+4g..32+4g+3}
    __shared__ __align__(16) float ksw[2][8][8][8];
    __shared__ __align__(16) float vsw[2][8][8][8];

    const int t    = threadIdx.x;
    const int tl   = t >> 7;        // token within CTA
    const int rr   = (t >> 1) & 63; // score row
    const int half = t & 1;         // which 32 columns
    const int base = blockIdx.x * 2;
    const size_t token = (size_t)(base + tl);

    // cooperative load with half-interleaving
    {
        const float4 vk = ((const float4*)(g_k + (size_t)base * HE))[t];
        const float4 vv = ((const float4*)(g_v + (size_t)base * HE))[t];
        const int th = t >> 4;      // tl*8 + h
        const int c  = t & 15;      // float4 within the 64-wide head row
        const int g  = c & 7;
        const int hh = c >> 3;      // which half this float4 belongs to
        float* kd = &ksw[0][0][0][0] + th * 64 + g * 8 + hh * 4;
        float* vd = &vsw[0][0][0][0] + th * 64 + g * 8 + hh * 4;
        *(float4*)kd = vk;
        *(float4*)vd = vv;
    }

    const float alpha = *alpha_p;
    const float am1 = alpha - 1.0f;
    const float inv = 1.0f / am1;
    const float qscale = am1 * 0.125f;   // fold am1 * (1/sqrt(64)) into q

    float qr[H];
#pragma unroll
    for (int h = 0; h < H; ++h)
        qr[h] = g_q[token * HE + h * 64 + rr] * qscale;

    __syncthreads();

    // packed score accumulation: s2[2g+d] holds cols (half*32+4g+2d, +1)
    ull s2[16];
#pragma unroll
    for (int u = 0; u < 16; ++u) s2[u] = 0ull;
#pragma unroll
    for (int h = 0; h < H; ++h) {
        const ull qh2 = pack2(qr[h], qr[h]);
        const ulonglong2* bp = (const ulonglong2*)&ksw[tl][h][0][0];
#pragma unroll
        for (int g = 0; g < 8; ++g) {
            ulonglong2 kk = bp[2 * g + half];
            s2[2 * g]     = ffma2(qh2, kk.x, s2[2 * g]);
            s2[2 * g + 1] = ffma2(qh2, kk.y, s2[2 * g + 1]);
        }
    }
    float s[32];
#pragma unroll
    for (int u = 0; u < 16; ++u) {
        float2 f = unpack2(s2[u]);
        s[2 * u] = f.x; s[2 * u + 1] = f.y;
    }

    float mx = s[0];
#pragma unroll
    for (int j = 1; j < 32; ++j) mx = fmaxf(mx, s[j]);
    mx = fmaxf(mx, __shfl_xor_sync(0xffffffffu, mx, 1));

    if (fabsf(inv - 2.0f) < 1e-4f) {
        // alpha = 1.5: p(z) = relu(z)^2. Newton from below + exact quadratic.
        float tau = mx - 1.0f;
        const float tau_hi = mx - 0.125f;
#pragma unroll 1
        for (int it = 0; it < 4; ++it) {
            float S1 = 0.f, S2 = 0.f;
#pragma unroll
            for (int j = 0; j < 32; ++j) {
                float z = fmaxf(s[j] - tau, 0.0f);
                S1 += z; S2 = fmaf(z, z, S2);
            }
            S1 += __shfl_xor_sync(0xffffffffu, S1, 1);
            S2 += __shfl_xor_sync(0xffffffffu, S2, 1);
            tau = fminf(tau + __fdividef(S2 - 1.0f, 2.0f * S1), tau_hi);
        }
        // exact solve: cnt*tau^2 - 2*S1*tau + (S2-1) = 0 on active set
        float s1 = 0.f, sq = 0.f, cnt = 0.f;
#pragma unroll
        for (int j = 0; j < 32; ++j) {
            float z = s[j] - tau;
            float m = fmaxf(z, 0.0f);
            s1 += m; sq = fmaf(m, m, sq);
            cnt += (z > 0.0f) ? 1.0f : 0.0f;
        }
        s1  += __shfl_xor_sync(0xffffffffu, s1, 1);
        sq  += __shfl_xor_sync(0xffffffffu, sq, 1);
        cnt += __shfl_xor_sync(0xffffffffu, cnt, 1);
        float S1 = fmaf(tau, cnt, s1);
        float S2 = sq + 2.0f * tau * s1 + tau * tau * cnt;
        float disc = fmaxf(fmaf(-cnt, S2 - 1.0f, S1 * S1), 0.0f);
        tau = __fdividef(S1 - sqrtf(disc), cnt);

        float sum = 0.f;
#pragma unroll
        for (int j = 0; j < 32; ++j) {
            float m = fmaxf(s[j] - tau, 0.0f);
            s[j] = m * m;
            sum += s[j];
        }
        sum += __shfl_xor_sync(0xffffffffu, sum, 1);
        float rn = __fdividef(1.0f, sum);
#pragma unroll
        for (int j = 0; j < 32; ++j) s[j] *= rn;
    } else {
        // generic alpha: faithful 50-iter bisection with pair reductions
        float tau_lo = mx - 1.0f;
        float dm = (mx - __powf(1.0f / 64.0f, am1)) - tau_lo;
        float part = 0.f;
#pragma unroll
        for (int j = 0; j < 32; ++j) {
            float z = s[j] - tau_lo;
            if (z > 0.0f) part += __powf(fmaxf(z, 1e-30f), inv);
        }
        part += __shfl_xor_sync(0xffffffffu, part, 1);
        const float f_lo = part - 1.0f;
        float tau_m = tau_lo;
#pragma unroll 1
        for (int it = 0; it < 50; ++it) {
            dm *= 0.5f;
            tau_m = tau_lo + dm;
            float pm = 0.f;
#pragma unroll
            for (int j = 0; j < 32; ++j) {
                float z = s[j] - tau_m;
                if (z > 0.0f) pm += __powf(fmaxf(z, 1e-30f), inv);
            }
            pm += __shfl_xor_sync(0xffffffffu, pm, 1);
            if ((pm - 1.0f) * f_lo >= 0.0f) tau_lo = tau_m;
        }
        float sum = 0.f;
#pragma unroll
        for (int j = 0; j < 32; ++j) {
            float z = s[j] - tau_m;
            s[j] = (z > 0.0f) ? __powf(fmaxf(z, 1e-30f), inv) : 0.0f;
            sum += s[j];
        }
        sum += __shfl_xor_sync(0xffffffffu, sum, 1);
        float rn = __fdividef(1.0f, sum);
#pragma unroll
        for (int j = 0; j < 32; ++j) s[j] *= rn;
    }

    // value mix: res[h][rr] = sum_j att[rr][j] * v[h][j]
    ull att2[16];
#pragma unroll
    for (int u = 0; u < 16; ++u) att2[u] = pack2(s[2 * u], s[2 * u + 1]);
#pragma unroll
    for (int h = 0; h < H; ++h) {
        ull racc = 0ull;
        const ulonglong2* bp = (const ulonglong2*)&vsw[tl][h][0][0];
#pragma unroll
        for (int g = 0; g < 8; ++g) {
            ulonglong2 vv = bp[2 * g + half];
            racc = ffma2(att2[2 * g],     vv.x, racc);
            racc = ffma2(att2[2 * g + 1], vv.y, racc);
        }
        float2 f = unpack2(racc);
        float rh = f.x + f.y;
        rh += __shfl_xor_sync(0xffffffffu, rh, 1);
        if (half == (h & 1))
            g_res[token * HE + h * 64 + rr] = rh;
    }
}

// ---------------------------------------------------------------------------
extern "C" void kernel_launch(void* const* d_in, const int* in_sizes, int n_in,
                              void* d_out, int out_size)
{
    const float* x     = (const float*)d_in[0];
    const float* alpha = (const float*)d_in[1];
    const float* Wk    = (const float*)d_in[2];
    const float* bk    = (const float*)d_in[3];
    const float* Wq    = (const float*)d_in[4];
    const float* bq    = (const float*)d_in[5];
    const float* Wv    = (const float*)d_in[6];
    const float* bv    = (const float*)d_in[7];
    const float* Wu    = (const float*)d_in[8];
    const float* bu    = (const float*)d_in[9];

    const int tokens = in_sizes[0] / E;   // 16384

    const int qkv_smem = (64 * 2 * 68 + 64 * 132) * sizeof(float);  // 68608
    const int out_smem = (64 * 2 * 68 + 64 * 68) * sizeof(float);   // 52224
    static int attr_done = 0;
    if (!attr_done) {
        cudaFuncSetAttribute(qkv_gemm, cudaFuncAttributeMaxDynamicSharedMemorySize, qkv_smem);
        cudaFuncSetAttribute(out_gemm, cudaFuncAttributeMaxDynamicSharedMemorySize, out_smem);
        attr_done = 1;
    }

    qkv_gemm<<<dim3(12, tokens / 128), 256, qkv_smem>>>(x, Wq, bq, Wk, bk, Wv, bv);
    attn_kernel<<<tokens / 2, 256>>>(alpha);
    out_gemm<<<tokens / 128, 256, out_smem>>>(Wu, bu, (float*)d_out);
}